// round 1
// baseline (speedup 1.0000x reference)
#include <cuda_runtime.h>

// EMA scan: s_t = 0.9*s_{t-1} + 0.1*x_t
// x: (T=1024, 32, 1024) f32, state: (32, 1024) f32
// out buffer: out (T*32768) followed by final_state (32768)

#define T_STEPS 1024
#define N_CH    32768      // 32 * 1024 independent channels
#define UNROLL  16

__global__ __launch_bounds__(256, 1)
void ema_scan_kernel(const float* __restrict__ x,
                     const float* __restrict__ state,
                     float* __restrict__ out)
{
    const int c = blockIdx.x * blockDim.x + threadIdx.x;  // channel id, 0..32767
    const float A = 0.9f;
    const float B = 1.0f - 0.9f;

    float s = state[c];

    const float* xp = x + c;
    float*       op = out + c;

    float xs[UNROLL];

    #pragma unroll 4
    for (int t0 = 0; t0 < T_STEPS; t0 += UNROLL) {
        // Batch-issue UNROLL independent loads (MLP=16 per thread)
        #pragma unroll
        for (int u = 0; u < UNROLL; u++) {
            xs[u] = xp[(size_t)(t0 + u) * N_CH];
        }
        // Serial FFMA chain (4 cyc/step), stores trail the chain
        #pragma unroll
        for (int u = 0; u < UNROLL; u++) {
            s = fmaf(s, A, xs[u] * B);
            op[(size_t)(t0 + u) * N_CH] = s;
        }
    }

    // final_state appended after out
    out[(size_t)T_STEPS * N_CH + c] = s;
}

extern "C" void kernel_launch(void* const* d_in, const int* in_sizes, int n_in,
                              void* d_out, int out_size)
{
    const float* x     = (const float*)d_in[0];
    const float* state = (const float*)d_in[1];
    float*       out   = (float*)d_out;

    dim3 block(256);
    dim3 grid(N_CH / 256);   // 128 CTAs, one thread per channel
    ema_scan_kernel<<<grid, block>>>(x, state, out);
}